// round 12
// baseline (speedup 1.0000x reference)
#include <cuda_runtime.h>
#include <math.h>

#define BB 32
#define NN 512
#define NH 4
#define NW 16
#define LOG2E 1.4426950408889634f

// ------------------------- scratch (device globals; no allocation) -------------------------
// h0/h1 live as tf32-bit, XOR-swizzled 64x128 tiles: elem (n, c) at
//   (b*NN + n)*128 + (c ^ ((n&3)<<3))
__device__ __align__(16) float    g_h0[(size_t)BB*NN*128];
__device__ float    g_s0[BB*NH*NN];   // pre-scaled by log2e
__device__ float    g_d0[BB*NH*NN];
__device__ __align__(16) float    g_h1[(size_t)BB*NN*128];
__device__ float    g_s1[BB*NN];      // pre-scaled by log2e
__device__ float    g_d1[BB*NN];
__device__ __align__(16) unsigned g_mask[BB*NN*NW];
// pre-converted (tf32 bits) + pre-swizzled weight tiles (64x128 each):
// tiles 0-1: W0 | 2-3: W1 | 4-7: linW | 8-9: meW0 | 10-11: meW1 | 12-13: ohW
__device__ __align__(16) float    g_wtf[14 * 8192];

// ------------------------- helpers -------------------------
__device__ __forceinline__ float qsum(float v) {
    v += __shfl_xor_sync(0xffffffffu, v, 1);
    v += __shfl_xor_sync(0xffffffffu, v, 2);
    return v;
}
__device__ __forceinline__ float gelu_exact(float v) {
    return 0.5f * v * (1.0f + erff(v * 0.70710678118654752f));
}
__device__ __forceinline__ unsigned f2tf(float f) {
    unsigned u; asm("cvt.rna.tf32.f32 %0, %1;" : "=r"(u) : "f"(f)); return u;
}
__device__ __forceinline__ float tfh(float f) { return __uint_as_float(f2tf(f)); }
__device__ __forceinline__ float ex2f(float x) {
    float y; asm("ex2.approx.f32 %0, %1;" : "=f"(y) : "f"(x)); return y;
}
__device__ __forceinline__ void mma_tf32(float c[4], const unsigned a[4], const unsigned b[2]) {
    asm volatile("mma.sync.aligned.m16n8k8.row.col.f32.tf32.tf32.f32 "
                 "{%0,%1,%2,%3}, {%4,%5,%6,%7}, {%8,%9}, {%0,%1,%2,%3};"
                 : "+f"(c[0]), "+f"(c[1]), "+f"(c[2]), "+f"(c[3])
                 : "r"(a[0]), "r"(a[1]), "r"(a[2]), "r"(a[3]), "r"(b[0]), "r"(b[1]));
}
__device__ __forceinline__ unsigned sptr(const void* p) {
    return (unsigned)__cvta_generic_to_shared(p);
}
// ldmatrix x4: loads the full tf32 m16k8 A-fragment in one instruction
__device__ __forceinline__ void ldsm4(unsigned r[4], unsigned saddr) {
    asm volatile("ldmatrix.sync.aligned.m8n8.x4.shared.b16 {%0,%1,%2,%3}, [%4];"
                 : "=r"(r[0]), "=r"(r[1]), "=r"(r[2]), "=r"(r[3]) : "r"(saddr));
}
__device__ __forceinline__ void cpa16(unsigned s, const void* g) {
    asm volatile("cp.async.cg.shared.global [%0], [%1], 16;" :: "r"(s), "l"(g));
}
#define CP_COMMIT asm volatile("cp.async.commit_group;")
#define CP_WAIT(n) asm volatile("cp.async.wait_group %0;" :: "n"(n))

// raw 16B-chunk copy of a 64x128-float tile (layout preserved)
__device__ __forceinline__ void issue_tile(float* dst, const float* __restrict__ src, int t) {
    for (int i = t; i < 2048; i += 256) cpa16(sptr(dst + i * 4), src + i * 4);
}
// raw copy of a 32x128-float half tile
__device__ __forceinline__ void issue_half(float* dst, const float* __restrict__ src, int t) {
    for (int i = t; i < 1024; i += 256) cpa16(sptr(dst + i * 4), src + i * 4);
}
// 64x128 tile with XOR swizzle applied on 16B granularity (raw fp32)
__device__ __forceinline__ void issue_wtile(float* dst, const float* __restrict__ src, int t) {
    for (int i = t; i < 2048; i += 256) {
        int r = i >> 5, c4 = (i & 31) * 4;
        cpa16(sptr(dst + r * 128 + (c4 ^ ((r & 3) << 3))), src + (size_t)r * 128 + c4);
    }
}

// ------------------------- prep: weights -> tf32 bits, swizzled tiles ----------------
__global__ void k_wprep(const float* __restrict__ W0, const float* __restrict__ W1,
                        const float* __restrict__ linW, const float* __restrict__ meW0,
                        const float* __restrict__ meW1, const float* __restrict__ ohW) {
    int c4i = blockIdx.x * 256 + threadIdx.x;        // float4 index, 28672 total
    int fl = c4i * 4;
    int T = fl >> 13;
    int off = fl & 8191;
    int r = off >> 7, cc = off & 127;
    const float* src; int rowbase;
    if (T < 2)       { src = W0;   rowbase = T * 64; }
    else if (T < 4)  { src = W1;   rowbase = (T - 2) * 64; }
    else if (T < 8)  { src = linW; rowbase = (T - 4) * 64; }
    else if (T < 10) { src = meW0; rowbase = (T - 8) * 64; }
    else if (T < 12) { src = meW1; rowbase = (T - 10) * 64; }
    else             { src = ohW;  rowbase = (T - 12) * 64; }
    float4 v = *(const float4*)&src[(size_t)(rowbase + r) * 128 + cc];
    float4 o; o.x = tfh(v.x); o.y = tfh(v.y); o.z = tfh(v.z); o.w = tfh(v.w);
    *(float4*)&g_wtf[T * 8192 + r * 128 + (cc ^ ((r & 3) << 3))] = o;
}

// ------------------------- proj0: h0 = X@W0 (64x128x128 per CTA) + s0/d0 -------------------
#define P0_SMEM ((8192 + 16384) * 4)

__global__ __launch_bounds__(256, 2) void k_proj0(const float* __restrict__ x,
                                                  const float* __restrict__ av,
                                                  const float* __restrict__ bv) {
    extern __shared__ float sm[];
    float* xs = sm;            // 64x128 raw fp32 swizzled A
    float* ws = xs + 8192;     // 2 x 64x128 tf32 swizzled W0

    int b = blockIdx.y, nb = blockIdx.x * 64;
    int t = threadIdx.x, w = t >> 5, lane = t & 31, g = lane >> 2, tg = lane & 3;
    int st = w & 1, ch = w >> 1;

    issue_wtile(xs, x + ((size_t)b * NN + nb) * 128, t);
    issue_tile(ws, g_wtf, t);
    CP_COMMIT;
    issue_tile(ws + 8192, g_wtf + 8192, t);
    CP_COMMIT;

    // ldmatrix lane-pointer geometry
    int q = lane >> 3, lr = lane & 7;
    int rowoff = (q & 1) * 8 + lr, colblk = (q >> 1) * 4;
    unsigned abase[2]; int asw[2];
#pragma unroll
    for (int mf = 0; mf < 2; mf++) {
        int row = st * 32 + mf * 16 + rowoff;
        abase[mf] = sptr(xs + row * 128);
        asw[mf] = (row & 3) << 3;
    }

    float c[2][4][4];
#pragma unroll
    for (int mf = 0; mf < 2; mf++)
#pragma unroll
        for (int j = 0; j < 4; j++)
#pragma unroll
            for (int e = 0; e < 4; e++) c[mf][j][e] = 0.0f;

#pragma unroll
    for (int kt = 0; kt < 2; kt++) {
        if (kt == 0) { CP_WAIT(1); } else { CP_WAIT(0); }
        __syncthreads();
        const float* wsb = ws + kt * 8192;
        for (int kc = 0; kc < 8; kc++) {
            unsigned a[2][4];
#pragma unroll
            for (int mf = 0; mf < 2; mf++) {
                unsigned raw[4];
                ldsm4(raw, abase[mf] + (((kt * 64 + kc * 8 + colblk) ^ asw[mf]) << 2));
                a[mf][0] = f2tf(__uint_as_float(raw[0]));
                a[mf][1] = f2tf(__uint_as_float(raw[1]));
                a[mf][2] = f2tf(__uint_as_float(raw[2]));
                a[mf][3] = f2tf(__uint_as_float(raw[3]));
            }
            int k0 = kc * 8 + tg, k1 = k0 + 4;
            int sw0 = tg << 3;
#pragma unroll
            for (int j = 0; j < 4; j++) {
                int f = ch * 32 + j * 8 + g;
                unsigned bfr[2];
                bfr[0] = __float_as_uint(wsb[k0 * 128 + (f ^ sw0)]);
                bfr[1] = __float_as_uint(wsb[k1 * 128 + (f ^ sw0)]);
                mma_tf32(c[0][j], a[0], bfr);
                mma_tf32(c[1][j], a[1], bfr);
            }
        }
    }

    // h0 write (tf32 swizzled)
#pragma unroll
    for (int mf = 0; mf < 2; mf++) {
        int row = st * 32 + mf * 16 + g;
        size_t base = ((size_t)b * NN + nb + row) * 128;
        int sw = (row & 3) << 3;
#pragma unroll
        for (int j = 0; j < 4; j++) {
            int col = (ch * 32 + j * 8 + 2 * tg) ^ sw;
            *(float2*)&g_h0[base + col] = make_float2(tfh(c[mf][j][0]), tfh(c[mf][j][1]));
            *(float2*)&g_h0[base + 8 * 128 + col] = make_float2(tfh(c[mf][j][2]), tfh(c[mf][j][3]));
        }
    }

    // s0/d0 (head == ch), pre-scaled by log2e
    float sv[2][2], dv[2][2];
#pragma unroll
    for (int mf = 0; mf < 2; mf++)
#pragma unroll
        for (int rr = 0; rr < 2; rr++) { sv[mf][rr] = 0.0f; dv[mf][rr] = 0.0f; }
#pragma unroll
    for (int mf = 0; mf < 2; mf++)
#pragma unroll
        for (int j = 0; j < 4; j++)
#pragma unroll
            for (int e = 0; e < 4; e++) {
                int col = ch * 32 + j * 8 + 2 * tg + (e & 1);
                sv[mf][e >> 1] += c[mf][j][e] * av[col];
                dv[mf][e >> 1] += c[mf][j][e] * bv[col];
            }
#pragma unroll
    for (int mf = 0; mf < 2; mf++)
#pragma unroll
        for (int rr = 0; rr < 2; rr++) {
            sv[mf][rr] = qsum(sv[mf][rr]);
            dv[mf][rr] = qsum(dv[mf][rr]);
        }
    if (tg == 0) {
#pragma unroll
        for (int mf = 0; mf < 2; mf++)
#pragma unroll
            for (int rr = 0; rr < 2; rr++) {
                int r = st * 32 + mf * 16 + g + rr * 8;
                g_s0[(b * NH + ch) * NN + nb + r] = sv[mf][rr] * LOG2E;
                g_d0[(b * NH + ch) * NN + nb + r] = dv[mf][rr] * LOG2E;
            }
    }
}

// ------------------------- attn0 fused: mask-gen + GAT0 softmax-agg + ELU + proj1 ----------
#define A0_SMEM ((16384 + 2048 + 1024 + 8192 + 128) * 4)

__global__ __launch_bounds__(256, 2) void k_attn0(const int* __restrict__ graph,
                                                  const float* __restrict__ av,
                                                  const float* __restrict__ bv) {
    extern __shared__ float sm[];
    float* sH = sm;                                // 2 x 64x128 (H tiles, later W1 tiles)
    float* sd = sH + 16384;                        // 4 x 512 d0
    unsigned* mk32 = (unsigned*)(sd + 2048);       // 1024 mask words
    float* xm = (float*)(mk32 + 1024);             // 64x128 m0 tile (tf32 swizzled)
    float* sdb = xm + 8192;                        // 128 (s1/d1 accum)

    int b = blockIdx.y, nb = blockIdx.x * 64;
    int t = threadIdx.x, w = t >> 5, lane = t & 31, g = lane >> 2, tg = lane & 3;
    int h = w >> 1, s0r = (w & 1) * 16;

    const float* Hsrc = g_h0 + (size_t)b * NN * 128;
    issue_tile(sH, Hsrc, t);
    CP_COMMIT;

    if (t < 128) sdb[t] = 0.0f;

    // mask generation for rows nb..nb+63 (ballot over graph)
    for (int wi = w; wi < 1024; wi += 8) {
        int row = wi >> 4, mq = wi & 15;
        int m = mq * 32 + lane, gn = nb + row;
        bool pred = (graph[((size_t)b * NN + gn) * NN + m] > 0) || (gn == m);
        unsigned bits = __ballot_sync(0xffffffffu, pred);
        if (lane == 0) mk32[wi] = bits;
    }
    for (int i = t; i < 2048; i += 256) sd[i] = g_d0[b * NH * NN + i];
    __syncthreads();
    // publish masks for attn1
    ((uint4*)(g_mask + (size_t)(b * NN + nb) * NW))[t] = ((uint4*)mk32)[t];

    const unsigned long long* mkq = (const unsigned long long*)mk32;

    int rows[4] = { s0r + g, s0r + g + 8, s0r + 32 + g, s0r + 40 + g };
    float srow[4], S[4];
#pragma unroll
    for (int rr = 0; rr < 4; rr++) {
        srow[rr] = g_s0[(b * NH + h) * NN + nb + rows[rr]];
        S[rr] = 0.0f;
    }
    float c[2][4][4];
#pragma unroll
    for (int sp = 0; sp < 2; sp++)
#pragma unroll
        for (int j = 0; j < 4; j++)
#pragma unroll
            for (int e = 0; e < 4; e++) c[sp][j][e] = 0.0f;

    const float* dh = sd + h * 512;

    for (int mt = 0; mt < 8; mt++) {
        CP_WAIT(0);
        __syncthreads();
        if (mt + 1 < 8) {
            issue_tile(sH + ((mt + 1) & 1) * 8192, Hsrc + (size_t)(mt + 1) * 8192, t);
            CP_COMMIT;
        } else {
            issue_tile(sH, g_wtf + 2 * 8192, t);   // W1 tile0 into sH[0] (free during mt=7)
            CP_COMMIT;
        }
        const float* Hb = sH + (mt & 1) * 8192;
        unsigned long long mw[4];
#pragma unroll
        for (int rr = 0; rr < 4; rr++) mw[rr] = mkq[rows[rr] * 8 + mt];
        const float* dmt = dh + mt * 64;

#pragma unroll
        for (int kc = 0; kc < 8; kc++) {
            int c0 = kc * 8 + tg, c1 = c0 + 4;
            float d0 = dmt[c0], d1 = dmt[c1];
            int sw0 = tg << 3;
            unsigned bfr[4][2];
#pragma unroll
            for (int j = 0; j < 4; j++) {
                int f = h * 32 + j * 8 + g;
                bfr[j][0] = __float_as_uint(Hb[c0 * 128 + (f ^ sw0)]);
                bfr[j][1] = __float_as_uint(Hb[c1 * 128 + (f ^ sw0)]);
            }
#pragma unroll
            for (int sp = 0; sp < 2; sp++) {
                int r0 = sp * 2, r1 = sp * 2 + 1;
                float z0 = srow[r0] + d0, z1 = srow[r1] + d0;
                float z2 = srow[r0] + d1, z3 = srow[r1] + d1;
                float p0 = ((mw[r0] >> c0) & 1ull) ? ex2f(fmaxf(z0, 0.2f * z0)) : 0.0f;
                float p1 = ((mw[r1] >> c0) & 1ull) ? ex2f(fmaxf(z1, 0.2f * z1)) : 0.0f;
                float p2 = ((mw[r0] >> c1) & 1ull) ? ex2f(fmaxf(z2, 0.2f * z2)) : 0.0f;
                float p3 = ((mw[r1] >> c1) & 1ull) ? ex2f(fmaxf(z3, 0.2f * z3)) : 0.0f;
                S[r0] += p0 + p2;
                S[r1] += p1 + p3;
                unsigned a[4] = { f2tf(p0), f2tf(p1), f2tf(p2), f2tf(p3) };
#pragma unroll
                for (int j = 0; j < 4; j++) mma_tf32(c[sp][j], a, bfr[j]);
            }
        }
    }
#pragma unroll
    for (int rr = 0; rr < 4; rr++) S[rr] = qsum(S[rr]);

    // m0 epilogue: /S, elu, tf32, into smem xm (swizzled)
#pragma unroll
    for (int sp = 0; sp < 2; sp++) {
        float inv0 = 1.0f / S[sp * 2], inv1 = 1.0f / S[sp * 2 + 1];
        int r0 = s0r + sp * 32 + g;
        int sw = (r0 & 3) << 3;
#pragma unroll
        for (int j = 0; j < 4; j++) {
            int col = (h * 32 + j * 8 + 2 * tg) ^ sw;
            float v0 = c[sp][j][0] * inv0, v1 = c[sp][j][1] * inv0;
            float v2 = c[sp][j][2] * inv1, v3 = c[sp][j][3] * inv1;
            v0 = v0 > 0.0f ? v0 : expm1f(v0);
            v1 = v1 > 0.0f ? v1 : expm1f(v1);
            v2 = v2 > 0.0f ? v2 : expm1f(v2);
            v3 = v3 > 0.0f ? v3 : expm1f(v3);
            *(float2*)&xm[r0 * 128 + col] = make_float2(tfh(v0), tfh(v1));
            *(float2*)&xm[(r0 + 8) * 128 + col] = make_float2(tfh(v2), tfh(v3));
        }
    }
    __syncthreads();                      // xm complete; sH[1] free
    issue_tile(sH + 8192, g_wtf + 3 * 8192, t);
    CP_COMMIT;

    // ---- fused proj1: h1 = m0 @ W1, 64x128x128 (A-frags via ldmatrix) ----
    int st2 = w & 1, ch2 = w >> 1;
    int q = lane >> 3, lr = lane & 7;
    int rowoff = (q & 1) * 8 + lr, colblk = (q >> 1) * 4;
    unsigned abase[2]; int asw[2];
#pragma unroll
    for (int mf = 0; mf < 2; mf++) {
        int row = st2 * 32 + mf * 16 + rowoff;
        abase[mf] = sptr(xm + row * 128);
        asw[mf] = (row & 3) << 3;
    }

    float c2[2][4][4];
#pragma unroll
    for (int mf = 0; mf < 2; mf++)
#pragma unroll
        for (int j = 0; j < 4; j++)
#pragma unroll
            for (int e = 0; e < 4; e++) c2[mf][j][e] = 0.0f;

#pragma unroll
    for (int kt = 0; kt < 2; kt++) {
        if (kt == 0) { CP_WAIT(1); } else { CP_WAIT(0); }
        __syncthreads();
        const float* wsb = sH + kt * 8192;
        for (int kc = 0; kc < 8; kc++) {
            unsigned a[2][4];
#pragma unroll
            for (int mf = 0; mf < 2; mf++)
                ldsm4(a[mf], abase[mf] + (((kt * 64 + kc * 8 + colblk) ^ asw[mf]) << 2));
            int k0 = kc * 8 + tg, k1 = k0 + 4;
            int sw0 = tg << 3;
#pragma unroll
            for (int j = 0; j < 4; j++) {
                int f = ch2 * 32 + j * 8 + g;
                unsigned bfr[2];
                bfr[0] = __float_as_uint(wsb[k0 * 128 + (f ^ sw0)]);
                bfr[1] = __float_as_uint(wsb[k1 * 128 + (f ^ sw0)]);
                mma_tf32(c2[0][j], a[0], bfr);
                mma_tf32(c2[1][j], a[1], bfr);
            }
        }
    }

    // h1 write (tf32 swizzled)
#pragma unroll
    for (int mf = 0; mf < 2; mf++) {
        int row = st2 * 32 + mf * 16 + g;
        size_t base = ((size_t)b * NN + nb + row) * 128;
        int sw = (row & 3) << 3;
#pragma unroll
        for (int j = 0; j < 4; j++) {
            int col = (ch2 * 32 + j * 8 + 2 * tg) ^ sw;
            *(float2*)&g_h1[base + col] = make_float2(tfh(c2[mf][j][0]), tfh(c2[mf][j][1]));
            *(float2*)&g_h1[base + 8 * 128 + col] = make_float2(tfh(c2[mf][j][2]), tfh(c2[mf][j][3]));
        }
    }

    // s1/d1 epilogue
    float sv[2][2], dv[2][2];
#pragma unroll
    for (int mf = 0; mf < 2; mf++)
#pragma unroll
        for (int rr = 0; rr < 2; rr++) { sv[mf][rr] = 0.0f; dv[mf][rr] = 0.0f; }
#pragma unroll
    for (int mf = 0; mf < 2; mf++)
#pragma unroll
        for (int j = 0; j < 4; j++)
#pragma unroll
            for (int e = 0; e < 4; e++) {
                int col = ch2 * 32 + j * 8 + 2 * tg + (e & 1);
                sv[mf][e >> 1] += c2[mf][j][e] * av[col];
                dv[mf][e >> 1] += c2[mf][j][e] * bv[col];
            }
#pragma unroll
    for (int mf = 0; mf < 2; mf++)
#pragma unroll
        for (int rr = 0; rr < 2; rr++) {
            sv[mf][rr] = qsum(sv[mf][rr]);
            dv[mf][rr] = qsum(dv[mf][rr]);
        }
    if (tg == 0) {
#pragma unroll
        for (int mf = 0; mf < 2; mf++)
#pragma unroll
            for (int rr = 0; rr < 2; rr++) {
                int r = st2 * 32 + mf * 16 + g + rr * 8;
                atomicAdd(&sdb[2 * r], sv[mf][rr]);
                atomicAdd(&sdb[2 * r + 1], dv[mf][rr]);
            }
    }
    __syncthreads();
    if (t < 64) {
        g_s1[b * NN + nb + t] = sdb[2 * t] * LOG2E;
        g_d1[b * NN + nb + t] = sdb[2 * t + 1] * LOG2E;
    }
}

// ------------------------- fused attn1 + tail -------------------------
#define A1T_SMEM ((17920 + 8192) * 4)

// A buffers hold tf32 BITS (CVT=false) or raw fp32 (CVT=true -> cvt after ldmatrix)
template<bool CVT>
__device__ __forceinline__ void tail_mm(const float* __restrict__ Wt, const float* A,
                                        int astride, int K, float* ws, float c[2][4][4],
                                        int st, int ch, int g, int tg, int lane, int t) {
    int q = lane >> 3, lr = lane & 7;
    int rowoff = (q & 1) * 8 + lr, colblk = (q >> 1) * 4;
    unsigned abase[2];
#pragma unroll
    for (int mf = 0; mf < 2; mf++)
        abase[mf] = sptr(A + (st * 32 + mf * 16 + rowoff) * astride + colblk);

    int NC = K >> 5;
    issue_half(ws, Wt, t);
    CP_COMMIT;
    for (int kt = 0; kt < NC; kt++) {
        if (kt + 1 < NC) {
            issue_half(ws + ((kt + 1) & 1) * 4096, Wt + (size_t)(kt + 1) * 4096, t);
            CP_COMMIT;
            CP_WAIT(1);
        } else {
            CP_WAIT(0);
        }
        __syncthreads();
        const float* wsb = ws + (kt & 1) * 4096;
        for (int kc = 0; kc < 4; kc++) {
            unsigned a[2][4];
#pragma unroll
            for (int mf = 0; mf < 2; mf++) {
                ldsm4(a[mf], abase[mf] + ((kt * 32 + kc * 8) << 2));
                if (CVT) {
                    a[mf][0] = f2tf(__uint_as_float(a[mf][0]));
                    a[mf][1] = f2tf(__uint_as_float(a[mf][1]));
                    a[mf][2] = f2tf(__uint_as_float(a[mf][2]));
                    a[mf][3] = f2tf(__uint_as_float(a[mf][3]));
                }
            }
            int k0 = kc * 8 + tg, k1 = k0 + 4;
            int sw0 = tg << 3;
#pragma unroll
            for (int j = 0; j < 4; j++) {
                int f = ch * 32 + j * 8 + g;
                unsigned bfr[2];
                bfr[0] = __float_as_uint(wsb[k0 * 128 + (f ^ sw0)]);
                bfr[1] = __float_as_uint(wsb[k1 * 128 + (f ^ sw0)]);
                mma_tf32(c[0][j], a[0], bfr);
                mma_tf32(c[1][j], a[1], bfr);
            }
        }
        __syncthreads();
    }
}

__device__ __forceinline__ void frag_store(float* D, int dstride, float c[2][4][4],
                                           int st, int ch, int g, int tg) {
#pragma unroll
    for (int mf = 0; mf < 2; mf++) {
        int row = st * 32 + mf * 16 + g;
#pragma unroll
        for (int j = 0; j < 4; j++) {
            int col = ch * 32 + j * 8 + 2 * tg;
            *(float2*)&D[row * dstride + col] = make_float2(c[mf][j][0], c[mf][j][1]);
            *(float2*)&D[(row + 8) * dstride + col] = make_float2(c[mf][j][2], c[mf][j][3]);
        }
    }
}

__device__ __forceinline__ void frag_zero(float c[2][4][4]) {
#pragma unroll
    for (int mf = 0; mf < 2; mf++)
#pragma unroll
        for (int j = 0; j < 4; j++)
#pragma unroll
            for (int e = 0; e < 4; e++) c[mf][j][e] = 0.0f;
}

__global__ __launch_bounds__(256, 2) void k_a1tail(const float* __restrict__ x,
                       const float* __restrict__ ln1g, const float* __restrict__ ln1b,
                       const float* __restrict__ linb,
                       const float* __restrict__ meb0, const float* __restrict__ meb1,
                       const float* __restrict__ ln2g, const float* __restrict__ ln2b,
                       const float* __restrict__ ohb,
                       const float* __restrict__ ln3g, const float* __restrict__ ln3b,
                       float* __restrict__ out) {
    extern __shared__ float sm[];
    float* sH = sm;                      // 2 x 64x128
    float* sd = sH + 16384;              // 512
    unsigned long long* mkq = (unsigned long long*)(sd + 512);  // 64 x 8
    float* ts = sm;                      // stride 260 (aliases sH/sd after attn)
    float* ms = sm;                      // stride 132
    float* us = sm + 8448;               // stride 132
    float* ws = sm + 17920;              // 2 x 32x128 weight chunks

    int b = blockIdx.y, nb = blockIdx.x * 64;
    int t = threadIdx.x, cq = t & 3, nl = t >> 2;
    int w = t >> 5, lane = t & 31, g = lane >> 2, tg = lane & 3;

    // ======== attn1 phase ========
    {
        int st = w & 3, ch = w >> 2;
        const float* Hsrc = g_h1 + (size_t)b * NN * 128;
        issue_tile(sH, Hsrc, t);
        CP_COMMIT;

        for (int i = t; i < 512; i += 256) sd[i] = g_d1[b * NN + i];
        {
            const unsigned long long* gq =
                (const unsigned long long*)(g_mask + (size_t)(b * NN + nb) * NW);
            for (int i = t; i < 512; i += 256) mkq[i] = gq[i];
        }

        int r0 = st * 16 + g, r1 = r0 + 8;
        float s0v = g_s1[b * NN + nb + r0];
        float s1v = g_s1[b * NN + nb + r1];
        float S0 = 0.0f, S1 = 0.0f;
        float c[8][4];
#pragma unroll
        for (int j = 0; j < 8; j++)
#pragma unroll
            for (int e = 0; e < 4; e++) c[j][e] = 0.0f;

        for (int mt = 0; mt < 8; mt++) {
            CP_WAIT(0);
            __syncthreads();
            if (mt + 1 < 8) {
                issue_tile(sH + ((mt + 1) & 1) * 8192, Hsrc + (size_t)(mt + 1) * 8192, t);
                CP_COMMIT;
            }
            const float* Hb = sH + (mt & 1) * 8192;
            unsigned long long mw0 = mkq[r0 * 8 + mt];
            unsigned long long mw1 = mkq[r1 * 8 + mt];
            const float* dmt = sd + mt * 64;

#pragma unroll
            for (int kc = 0; kc < 8; kc++) {
                int c0 = kc * 8 + tg, c1 = c0 + 4;
                float d0 = dmt[c0], d1 = dmt[c1];
                float z0 = s0v + d0, z1 = s1v + d0;
                float z2 = s0v + d1, z3 = s1v + d1;
                float p0 = ((mw0 >> c0) & 1ull) ? ex2f(fmaxf(z0, 0.2f * z0)) : 0.0f;
                float p1 = ((mw1 >> c0) & 1ull) ? ex2f(fmaxf(z1, 0.2f * z1)) : 0.0f;
                float p2 = ((mw0 >> c1) & 1ull) ? ex2f(fmaxf(z2, 0.2f * z2)) : 0.0f;
                float p3 = ((mw1 >> c1) & 1ull) ? ex2f(fmaxf(z3, 0.2f * z3)) : 0.0f;
                S0 += p0 + p2;
                S1 += p1 + p3;
                unsigned a[4] = { f2tf(p0), f2tf(p1), f2tf(p2), f2tf(p3) };
                int sw0 = tg << 3;
#pragma unroll
                for (int j = 0; j < 8; j++) {
                    int f = ch * 64 + j * 8 + g;
                    unsigned bfr[2];
                    bfr[0] = __float_as_uint(Hb[c0 * 128 + (f ^ sw0)]);
                    bfr[1] = __float_as_uint(Hb[c1 * 128 + (f ^ sw0)]);
                    mma_tf32(c[j], a, bfr);
                }
            }
        }
        S0 = qsum(S0); S1 = qsum(S1);
        float inv0 = 1.0f / S0, inv1 = 1.0f / S1;

        __syncthreads();   // everyone done reading sH/sd; ts overwrite is safe

        // x -> ts cols 0..127 (async), m1 -> ts cols 128..255 (from registers)
        for (int i = t; i < 2048; i += 256) {
            int r = i >> 5, c4 = (i & 31) * 4;
            cpa16(sptr(ts + r * 260 + c4), x + ((size_t)(b * NN + nb) + r) * 128 + c4);
        }
        CP_COMMIT;
#pragma unroll
        for (int j = 0; j < 8; j++) {
            int col = 128 + ch * 64 + j * 8 + 2 * tg;
            *(float2*)&ts[r0 * 260 + col] = make_float2(c[j][0] * inv0, c[j][1] * inv0);
            *(float2*)&ts[(r0 + 8) * 260 + col] = make_float2(c[j][2] * inv1, c[j][3] * inv1);
        }
        CP_WAIT(0);
        __syncthreads();
    }

    // ======== tail phase ========
    int st = w & 1, ch = w >> 1;

    // LN1 over 256 (stats on raw fp32; output stored as tf32 bits for mm1)
    float sum = 0, sq = 0;
#pragma unroll 8
    for (int i = 0; i < 64; i++) {
        float v = ts[nl * 260 + cq * 64 + i];
        sum += v; sq += v * v;
    }
    sum = qsum(sum); sq = qsum(sq);
    float mu = sum * (1.0f / 256.0f);
    float rstd = rsqrtf(sq * (1.0f / 256.0f) - mu * mu + 1e-5f);
#pragma unroll 8
    for (int i = 0; i < 64; i++) {
        int j = cq * 64 + i;
        float v = ts[nl * 260 + j];
        ts[nl * 260 + j] = tfh((v - mu) * rstd * ln1g[j] + ln1b[j]);
    }

    float c[2][4][4];
    // mm1: m = LN1 @ linW   (A = ts holds tf32 bits)
    frag_zero(c);
    tail_mm<false>(g_wtf + 4 * 8192, ts, 260, 256, ws, c, st, ch, g, tg, lane, t);
    frag_store(ms, 132, c, st, ch, g, tg);
    __syncthreads();
    // m stored as RAW fp32 (residual source); mm2 converts at A-load time
#pragma unroll
    for (int d = 0; d < 32; d++) {
        int o = cq * 32 + d;
        ms[nl * 132 + o] = ms[nl * 132 + o] + linb[o];
    }
    __syncthreads();

    // mm2: u = gelu(m @ meW0 + meb0)   (A = ms raw fp32 -> CVT=true)
    frag_zero(c);
    tail_mm<true>(g_wtf + 8 * 8192, ms, 132, 128, ws, c, st, ch, g, tg, lane, t);
    frag_store(us, 132, c, st, ch, g, tg);
    __syncthreads();
#pragma unroll
    for (int d = 0; d < 32; d++) {
        int o = cq * 32 + d;
        us[nl * 132 + o] = tfh(gelu_exact(us[nl * 132 + o] + meb0[o]));
    }

    // mm3: enc = u @ meW1; r = m + enc + meb1; LN2 -> us (tf32)
    frag_zero(c);
    tail_mm<false>(g_wtf + 10 * 8192, us, 132, 128, ws, c, st, ch, g, tg, lane, t);
    // ms still holds fp32 m; snapshot own rows BEFORE overwriting with enc frags
    float mtmp[32];
#pragma unroll
    for (int d = 0; d < 32; d++) mtmp[d] = ms[nl * 132 + cq * 32 + d];
    __syncthreads();
    frag_store(ms, 132, c, st, ch, g, tg);
    __syncthreads();
    float a3[32];
    sum = 0; sq = 0;
#pragma unroll
    for (int d = 0; d < 32; d++) {
        int o = cq * 32 + d;
        a3[d] = ms[nl * 132 + o] + meb1[o] + mtmp[d];
        sum += a3[d]; sq += a3[d] * a3[d];
    }
    sum = qsum(sum); sq = qsum(sq);
    mu = sum * (1.0f / 128.0f);
    rstd = rsqrtf(sq * (1.0f / 128.0f) - mu * mu + 1e-5f);
    __syncthreads();
#pragma unroll
    for (int d = 0; d < 32; d++) {
        int o = cq * 32 + d;
        us[nl * 132 + o] = tfh((a3[d] - mu) * rstd * ln2g[o] + ln2b[o]);
    }

    // mm4: v = gelu(us @ ohW + ohb); LN3; out
    frag_zero(c);
    tail_mm<false>(g_wtf + 12 * 8192, us, 132, 128, ws, c, st, ch, g, tg, lane, t);
    frag_store(ms, 132, c, st, ch, g, tg);
    __syncthreads();
    float a4[32];
    sum = 0; sq = 0;
#pragma unroll
    for (int d = 0; d < 32; d++) {
        int o = cq * 32 + d;
        float v = gelu_exact(ms[nl * 132 + o] + ohb[o]);
        a4[d] = v;
        sum += v; sq += v * v;
    }
    sum = qsum(sum); sq = qsum(sq);
    mu = sum * (1.0f / 128.0f);
    rstd = rsqrtf(sq * (1.0f / 128.0f) - mu * mu + 1e-5f);

    float* op = out + ((size_t)b * NN + nb + nl) * 128 + cq * 32;
#pragma unroll
    for (int d4 = 0; d4 < 8; d4++) {
        float r0 = (a4[4 * d4 + 0] - mu) * rstd * ln3g[cq * 32 + 4 * d4 + 0] + ln3b[cq * 32 + 4 * d4 + 0];
        float r1 = (a4[4 * d4 + 1] - mu) * rstd * ln3g[cq * 32 + 4 * d4 + 1] + ln3b[cq * 32 + 4 * d4 + 1];
        float r2 = (a4[4 * d4 + 2] - mu) * rstd * ln3g[cq * 32 + 4 * d4 + 2] + ln3b[cq * 32 + 4 * d4 + 2];
        float r3 = (a4[4 * d4 + 3] - mu) * rstd * ln3g[cq * 32 + 4 * d4 + 3] + ln3b[cq * 32 + 4 * d4 + 3];
        ((float4*)op)[d4] = make_float4(r0, r1, r2, r3);
    }
}

// ------------------------- launch -------------------------
extern "C" void kernel_launch(void* const* d_in, const int* in_sizes, int n_in,
                              void* d_out, int out_size) {
    const float* x    = (const float*)d_in[0];
    const int*   grp  = (const int*)  d_in[1];
    const float* W0   = (const float*)d_in[2];
    const float* as0  = (const float*)d_in[3];
    const float* ad0  = (const float*)d_in[4];
    const float* W1   = (const float*)d_in[5];
    const float* as1  = (const float*)d_in[6];
    const float* ad1  = (const float*)d_in[7];
    const float* ln1g = (const float*)d_in[8];
    const float* ln1b = (const float*)d_in[9];
    const float* linW = (const float*)d_in[10];
    const float* linb = (const float*)d_in[11];
    const float* meW0 = (const float*)d_in[12];
    const float* meb0 = (const float*)d_in[13];
    const float* meW1 = (const float*)d_in[14];
    const float* meb1 = (const float*)d_in[15];
    const float* ln2g = (const float*)d_in[16];
    const float* ln2b = (const float*)d_in[17];
    const float* ohW  = (const float*)d_in[18];
    const float* ohb  = (const float*)d_in[19];
    const float* ln3g = (const float*)d_in[20];
    const float* ln3b = (const float*)d_in[21];
    float* out = (float*)d_out;

    cudaFuncSetAttribute(k_proj0, cudaFuncAttributeMaxDynamicSharedMemorySize, P0_SMEM);
    cudaFuncSetAttribute(k_attn0, cudaFuncAttributeMaxDynamicSharedMemorySize, A0_SMEM);
    cudaFuncSetAttribute(k_a1tail, cudaFuncAttributeMaxDynamicSharedMemorySize, A1T_SMEM);

    dim3 grid(NN / 64, BB);
    k_wprep<<<112, 256>>>(W0, W1, linW, meW0, meW1, ohW);
    k_proj0<<<grid, 256, P0_SMEM>>>(x, as0, ad0);
    k_attn0<<<grid, 256, A0_SMEM>>>(grp, as1, ad1);
    k_a1tail<<<grid, 256, A1T_SMEM>>>(x, ln1g, ln1b, linb, meb0, meb1,
                                      ln2g, ln2b, ohb, ln3g, ln3b, out);
}

// round 13
// speedup vs baseline: 1.0241x; 1.0241x over previous
#include <cuda_runtime.h>
#include <math.h>

#define BB 32
#define NN 512
#define NH 4
#define NW 16
#define LOG2E 1.4426950408889634f

// ------------------------- scratch (device globals; no allocation) -------------------------
// h0/h1 live as tf32-bit, XOR-swizzled 64x128 tiles: elem (n, c) at
//   (b*NN + n)*128 + (c ^ ((n&3)<<3))
__device__ __align__(16) float    g_h0[(size_t)BB*NN*128];
__device__ float    g_s0[BB*NH*NN];   // pre-scaled by log2e
__device__ float    g_d0[BB*NH*NN];
__device__ __align__(16) float    g_h1[(size_t)BB*NN*128];
__device__ float    g_s1[BB*NN];      // pre-scaled by log2e
__device__ float    g_d1[BB*NN];
__device__ __align__(16) unsigned g_mask[BB*NN*NW];
// pre-converted (tf32 bits) + pre-swizzled weight tiles (64x128 each):
// tiles 0-1: W0 | 2-3: W1 | 4-7: linW | 8-9: meW0 | 10-11: meW1 | 12-13: ohW
__device__ __align__(16) float    g_wtf[14 * 8192];

// ------------------------- helpers -------------------------
__device__ __forceinline__ float qsum(float v) {
    v += __shfl_xor_sync(0xffffffffu, v, 1);
    v += __shfl_xor_sync(0xffffffffu, v, 2);
    return v;
}
__device__ __forceinline__ float gelu_exact(float v) {
    return 0.5f * v * (1.0f + erff(v * 0.70710678118654752f));
}
__device__ __forceinline__ unsigned f2tf(float f) {
    unsigned u; asm("cvt.rna.tf32.f32 %0, %1;" : "=r"(u) : "f"(f)); return u;
}
__device__ __forceinline__ float tfh(float f) { return __uint_as_float(f2tf(f)); }
__device__ __forceinline__ float ex2f(float x) {
    float y; asm("ex2.approx.f32 %0, %1;" : "=f"(y) : "f"(x)); return y;
}
__device__ __forceinline__ void mma_tf32(float c[4], const unsigned a[4], const unsigned b[2]) {
    asm volatile("mma.sync.aligned.m16n8k8.row.col.f32.tf32.tf32.f32 "
                 "{%0,%1,%2,%3}, {%4,%5,%6,%7}, {%8,%9}, {%0,%1,%2,%3};"
                 : "+f"(c[0]), "+f"(c[1]), "+f"(c[2]), "+f"(c[3])
                 : "r"(a[0]), "r"(a[1]), "r"(a[2]), "r"(a[3]), "r"(b[0]), "r"(b[1]));
}
__device__ __forceinline__ unsigned sptr(const void* p) {
    return (unsigned)__cvta_generic_to_shared(p);
}
// ldmatrix x4: loads the full tf32 m16k8 A-fragment in one instruction
__device__ __forceinline__ void ldsm4(unsigned r[4], unsigned saddr) {
    asm volatile("ldmatrix.sync.aligned.m8n8.x4.shared.b16 {%0,%1,%2,%3}, [%4];"
                 : "=r"(r[0]), "=r"(r[1]), "=r"(r[2]), "=r"(r[3]) : "r"(saddr));
}
__device__ __forceinline__ void cpa16(unsigned s, const void* g) {
    asm volatile("cp.async.cg.shared.global [%0], [%1], 16;" :: "r"(s), "l"(g));
}
#define CP_COMMIT asm volatile("cp.async.commit_group;")
#define CP_WAIT(n) asm volatile("cp.async.wait_group %0;" :: "n"(n))

// raw 16B-chunk copy of a 64x128-float tile (layout preserved)
__device__ __forceinline__ void issue_tile(float* dst, const float* __restrict__ src, int t) {
    for (int i = t; i < 2048; i += 256) cpa16(sptr(dst + i * 4), src + i * 4);
}
// raw copy of a 32x128-float half tile
__device__ __forceinline__ void issue_half(float* dst, const float* __restrict__ src, int t) {
    for (int i = t; i < 1024; i += 256) cpa16(sptr(dst + i * 4), src + i * 4);
}
// 64x128 tile with XOR swizzle applied on 16B granularity (raw fp32)
__device__ __forceinline__ void issue_wtile(float* dst, const float* __restrict__ src, int t) {
    for (int i = t; i < 2048; i += 256) {
        int r = i >> 5, c4 = (i & 31) * 4;
        cpa16(sptr(dst + r * 128 + (c4 ^ ((r & 3) << 3))), src + (size_t)r * 128 + c4);
    }
}

// ------------------------- prep: weights -> tf32 bits, swizzled tiles ----------------
__global__ void k_wprep(const float* __restrict__ W0, const float* __restrict__ W1,
                        const float* __restrict__ linW, const float* __restrict__ meW0,
                        const float* __restrict__ meW1, const float* __restrict__ ohW) {
    int c4i = blockIdx.x * 256 + threadIdx.x;        // float4 index, 28672 total
    int fl = c4i * 4;
    int T = fl >> 13;
    int off = fl & 8191;
    int r = off >> 7, cc = off & 127;
    const float* src; int rowbase;
    if (T < 2)       { src = W0;   rowbase = T * 64; }
    else if (T < 4)  { src = W1;   rowbase = (T - 2) * 64; }
    else if (T < 8)  { src = linW; rowbase = (T - 4) * 64; }
    else if (T < 10) { src = meW0; rowbase = (T - 8) * 64; }
    else if (T < 12) { src = meW1; rowbase = (T - 10) * 64; }
    else             { src = ohW;  rowbase = (T - 12) * 64; }
    float4 v = *(const float4*)&src[(size_t)(rowbase + r) * 128 + cc];
    float4 o; o.x = tfh(v.x); o.y = tfh(v.y); o.z = tfh(v.z); o.w = tfh(v.w);
    *(float4*)&g_wtf[T * 8192 + r * 128 + (cc ^ ((r & 3) << 3))] = o;
}

// ------------------------- proj0: h0 = X@W0 (64x128x128 per CTA) + s0/d0 -------------------
#define P0_SMEM ((8192 + 16384) * 4)

__global__ __launch_bounds__(256, 2) void k_proj0(const float* __restrict__ x,
                                                  const float* __restrict__ av,
                                                  const float* __restrict__ bv) {
    extern __shared__ float sm[];
    float* xs = sm;            // 64x128 raw fp32 swizzled A
    float* ws = xs + 8192;     // 2 x 64x128 tf32 swizzled W0

    int b = blockIdx.y, nb = blockIdx.x * 64;
    int t = threadIdx.x, w = t >> 5, lane = t & 31, g = lane >> 2, tg = lane & 3;
    int st = w & 1, ch = w >> 1;

    issue_wtile(xs, x + ((size_t)b * NN + nb) * 128, t);
    issue_tile(ws, g_wtf, t);
    CP_COMMIT;
    issue_tile(ws + 8192, g_wtf + 8192, t);
    CP_COMMIT;

    // ldmatrix lane-pointer geometry
    int q = lane >> 3, lr = lane & 7;
    int rowoff = (q & 1) * 8 + lr, colblk = (q >> 1) * 4;
    unsigned abase[2]; int asw[2];
#pragma unroll
    for (int mf = 0; mf < 2; mf++) {
        int row = st * 32 + mf * 16 + rowoff;
        abase[mf] = sptr(xs + row * 128);
        asw[mf] = (row & 3) << 3;
    }

    float c[2][4][4];
#pragma unroll
    for (int mf = 0; mf < 2; mf++)
#pragma unroll
        for (int j = 0; j < 4; j++)
#pragma unroll
            for (int e = 0; e < 4; e++) c[mf][j][e] = 0.0f;

#pragma unroll
    for (int kt = 0; kt < 2; kt++) {
        if (kt == 0) { CP_WAIT(1); } else { CP_WAIT(0); }
        __syncthreads();
        const float* wsb = ws + kt * 8192;
        for (int kc = 0; kc < 8; kc++) {
            unsigned a[2][4];
#pragma unroll
            for (int mf = 0; mf < 2; mf++) {
                unsigned raw[4];
                ldsm4(raw, abase[mf] + (((kt * 64 + kc * 8 + colblk) ^ asw[mf]) << 2));
                a[mf][0] = f2tf(__uint_as_float(raw[0]));
                a[mf][1] = f2tf(__uint_as_float(raw[1]));
                a[mf][2] = f2tf(__uint_as_float(raw[2]));
                a[mf][3] = f2tf(__uint_as_float(raw[3]));
            }
            int k0 = kc * 8 + tg, k1 = k0 + 4;
            int sw0 = tg << 3;
#pragma unroll
            for (int j = 0; j < 4; j++) {
                int f = ch * 32 + j * 8 + g;
                unsigned bfr[2];
                bfr[0] = __float_as_uint(wsb[k0 * 128 + (f ^ sw0)]);
                bfr[1] = __float_as_uint(wsb[k1 * 128 + (f ^ sw0)]);
                mma_tf32(c[0][j], a[0], bfr);
                mma_tf32(c[1][j], a[1], bfr);
            }
        }
    }

    // h0 write (tf32 swizzled)
#pragma unroll
    for (int mf = 0; mf < 2; mf++) {
        int row = st * 32 + mf * 16 + g;
        size_t base = ((size_t)b * NN + nb + row) * 128;
        int sw = (row & 3) << 3;
#pragma unroll
        for (int j = 0; j < 4; j++) {
            int col = (ch * 32 + j * 8 + 2 * tg) ^ sw;
            *(float2*)&g_h0[base + col] = make_float2(tfh(c[mf][j][0]), tfh(c[mf][j][1]));
            *(float2*)&g_h0[base + 8 * 128 + col] = make_float2(tfh(c[mf][j][2]), tfh(c[mf][j][3]));
        }
    }

    // s0/d0 (head == ch), pre-scaled by log2e
    float sv[2][2], dv[2][2];
#pragma unroll
    for (int mf = 0; mf < 2; mf++)
#pragma unroll
        for (int rr = 0; rr < 2; rr++) { sv[mf][rr] = 0.0f; dv[mf][rr] = 0.0f; }
#pragma unroll
    for (int mf = 0; mf < 2; mf++)
#pragma unroll
        for (int j = 0; j < 4; j++)
#pragma unroll
            for (int e = 0; e < 4; e++) {
                int col = ch * 32 + j * 8 + 2 * tg + (e & 1);
                sv[mf][e >> 1] += c[mf][j][e] * av[col];
                dv[mf][e >> 1] += c[mf][j][e] * bv[col];
            }
#pragma unroll
    for (int mf = 0; mf < 2; mf++)
#pragma unroll
        for (int rr = 0; rr < 2; rr++) {
            sv[mf][rr] = qsum(sv[mf][rr]);
            dv[mf][rr] = qsum(dv[mf][rr]);
        }
    if (tg == 0) {
#pragma unroll
        for (int mf = 0; mf < 2; mf++)
#pragma unroll
            for (int rr = 0; rr < 2; rr++) {
                int r = st * 32 + mf * 16 + g + rr * 8;
                g_s0[(b * NH + ch) * NN + nb + r] = sv[mf][rr] * LOG2E;
                g_d0[(b * NH + ch) * NN + nb + r] = dv[mf][rr] * LOG2E;
            }
    }
}

// ------------------------- attn0 fused: mask-gen + GAT0 softmax-agg + ELU + proj1 ----------
#define A0_SMEM ((16384 + 2048 + 1024 + 8192 + 128) * 4)

__global__ __launch_bounds__(256, 2) void k_attn0(const int* __restrict__ graph,
                                                  const float* __restrict__ av,
                                                  const float* __restrict__ bv) {
    extern __shared__ float sm[];
    float* sH = sm;                                // 2 x 64x128 (H tiles, later W1 tiles)
    float* sd = sH + 16384;                        // 4 x 512 d0
    unsigned* mk32 = (unsigned*)(sd + 2048);       // 1024 mask words
    float* xm = (float*)(mk32 + 1024);             // 64x128 m0 tile (tf32 swizzled)
    float* sdb = xm + 8192;                        // 128 (s1/d1 accum)

    int b = blockIdx.y, nb = blockIdx.x * 64;
    int t = threadIdx.x, w = t >> 5, lane = t & 31, g = lane >> 2, tg = lane & 3;
    int h = w >> 1, s0r = (w & 1) * 16;

    const float* Hsrc = g_h0 + (size_t)b * NN * 128;
    issue_tile(sH, Hsrc, t);
    CP_COMMIT;

    if (t < 128) sdb[t] = 0.0f;

    // mask generation for rows nb..nb+63 (ballot over graph)
    for (int wi = w; wi < 1024; wi += 8) {
        int row = wi >> 4, mq = wi & 15;
        int m = mq * 32 + lane, gn = nb + row;
        bool pred = (graph[((size_t)b * NN + gn) * NN + m] > 0) || (gn == m);
        unsigned bits = __ballot_sync(0xffffffffu, pred);
        if (lane == 0) mk32[wi] = bits;
    }
    for (int i = t; i < 2048; i += 256) sd[i] = g_d0[b * NH * NN + i];
    __syncthreads();
    // publish masks for attn1
    ((uint4*)(g_mask + (size_t)(b * NN + nb) * NW))[t] = ((uint4*)mk32)[t];

    const unsigned long long* mkq = (const unsigned long long*)mk32;

    int rows[4] = { s0r + g, s0r + g + 8, s0r + 32 + g, s0r + 40 + g };
    float srow[4], S[4];
#pragma unroll
    for (int rr = 0; rr < 4; rr++) {
        srow[rr] = g_s0[(b * NH + h) * NN + nb + rows[rr]];
        S[rr] = 0.0f;
    }
    float c[2][4][4];
#pragma unroll
    for (int sp = 0; sp < 2; sp++)
#pragma unroll
        for (int j = 0; j < 4; j++)
#pragma unroll
            for (int e = 0; e < 4; e++) c[sp][j][e] = 0.0f;

    const float* dh = sd + h * 512;

    for (int mt = 0; mt < 8; mt++) {
        CP_WAIT(0);
        __syncthreads();
        if (mt + 1 < 8) {
            issue_tile(sH + ((mt + 1) & 1) * 8192, Hsrc + (size_t)(mt + 1) * 8192, t);
            CP_COMMIT;
        } else {
            issue_tile(sH, g_wtf + 2 * 8192, t);   // W1 tile0 into sH[0] (free during mt=7)
            CP_COMMIT;
        }
        const float* Hb = sH + (mt & 1) * 8192;
        unsigned long long mw[4];
#pragma unroll
        for (int rr = 0; rr < 4; rr++) mw[rr] = mkq[rows[rr] * 8 + mt];
        const float* dmt = dh + mt * 64;

#pragma unroll
        for (int kc = 0; kc < 8; kc++) {
            int c0 = kc * 8 + tg, c1 = c0 + 4;
            float d0 = dmt[c0], d1 = dmt[c1];
            int sw0 = tg << 3;
            unsigned bfr[4][2];
#pragma unroll
            for (int j = 0; j < 4; j++) {
                int f = h * 32 + j * 8 + g;
                bfr[j][0] = __float_as_uint(Hb[c0 * 128 + (f ^ sw0)]);
                bfr[j][1] = __float_as_uint(Hb[c1 * 128 + (f ^ sw0)]);
            }
#pragma unroll
            for (int sp = 0; sp < 2; sp++) {
                int r0 = sp * 2, r1 = sp * 2 + 1;
                float z0 = srow[r0] + d0, z1 = srow[r1] + d0;
                float z2 = srow[r0] + d1, z3 = srow[r1] + d1;
                float p0 = ((mw[r0] >> c0) & 1ull) ? ex2f(fmaxf(z0, 0.2f * z0)) : 0.0f;
                float p1 = ((mw[r1] >> c0) & 1ull) ? ex2f(fmaxf(z1, 0.2f * z1)) : 0.0f;
                float p2 = ((mw[r0] >> c1) & 1ull) ? ex2f(fmaxf(z2, 0.2f * z2)) : 0.0f;
                float p3 = ((mw[r1] >> c1) & 1ull) ? ex2f(fmaxf(z3, 0.2f * z3)) : 0.0f;
                S[r0] += p0 + p2;
                S[r1] += p1 + p3;
                unsigned a[4] = { f2tf(p0), f2tf(p1), f2tf(p2), f2tf(p3) };
#pragma unroll
                for (int j = 0; j < 4; j++) mma_tf32(c[sp][j], a, bfr[j]);
            }
        }
    }
#pragma unroll
    for (int rr = 0; rr < 4; rr++) S[rr] = qsum(S[rr]);

    // m0 epilogue: /S, elu, tf32, into smem xm (swizzled)
#pragma unroll
    for (int sp = 0; sp < 2; sp++) {
        float inv0 = 1.0f / S[sp * 2], inv1 = 1.0f / S[sp * 2 + 1];
        int r0 = s0r + sp * 32 + g;
        int sw = (r0 & 3) << 3;
#pragma unroll
        for (int j = 0; j < 4; j++) {
            int col = (h * 32 + j * 8 + 2 * tg) ^ sw;
            float v0 = c[sp][j][0] * inv0, v1 = c[sp][j][1] * inv0;
            float v2 = c[sp][j][2] * inv1, v3 = c[sp][j][3] * inv1;
            v0 = v0 > 0.0f ? v0 : expm1f(v0);
            v1 = v1 > 0.0f ? v1 : expm1f(v1);
            v2 = v2 > 0.0f ? v2 : expm1f(v2);
            v3 = v3 > 0.0f ? v3 : expm1f(v3);
            *(float2*)&xm[r0 * 128 + col] = make_float2(tfh(v0), tfh(v1));
            *(float2*)&xm[(r0 + 8) * 128 + col] = make_float2(tfh(v2), tfh(v3));
        }
    }
    __syncthreads();                      // xm complete; sH[1] free
    issue_tile(sH + 8192, g_wtf + 3 * 8192, t);
    CP_COMMIT;

    // ---- fused proj1: h1 = m0 @ W1, 64x128x128 (A-frags via ldmatrix) ----
    int st2 = w & 1, ch2 = w >> 1;
    int q = lane >> 3, lr = lane & 7;
    int rowoff = (q & 1) * 8 + lr, colblk = (q >> 1) * 4;
    unsigned abase[2]; int asw[2];
#pragma unroll
    for (int mf = 0; mf < 2; mf++) {
        int row = st2 * 32 + mf * 16 + rowoff;
        abase[mf] = sptr(xm + row * 128);
        asw[mf] = (row & 3) << 3;
    }

    float c2[2][4][4];
#pragma unroll
    for (int mf = 0; mf < 2; mf++)
#pragma unroll
        for (int j = 0; j < 4; j++)
#pragma unroll
            for (int e = 0; e < 4; e++) c2[mf][j][e] = 0.0f;

#pragma unroll
    for (int kt = 0; kt < 2; kt++) {
        if (kt == 0) { CP_WAIT(1); } else { CP_WAIT(0); }
        __syncthreads();
        const float* wsb = sH + kt * 8192;
        for (int kc = 0; kc < 8; kc++) {
            unsigned a[2][4];
#pragma unroll
            for (int mf = 0; mf < 2; mf++)
                ldsm4(a[mf], abase[mf] + (((kt * 64 + kc * 8 + colblk) ^ asw[mf]) << 2));
            int k0 = kc * 8 + tg, k1 = k0 + 4;
            int sw0 = tg << 3;
#pragma unroll
            for (int j = 0; j < 4; j++) {
                int f = ch2 * 32 + j * 8 + g;
                unsigned bfr[2];
                bfr[0] = __float_as_uint(wsb[k0 * 128 + (f ^ sw0)]);
                bfr[1] = __float_as_uint(wsb[k1 * 128 + (f ^ sw0)]);
                mma_tf32(c2[0][j], a[0], bfr);
                mma_tf32(c2[1][j], a[1], bfr);
            }
        }
    }

    // h1 write (tf32 swizzled)
#pragma unroll
    for (int mf = 0; mf < 2; mf++) {
        int row = st2 * 32 + mf * 16 + g;
        size_t base = ((size_t)b * NN + nb + row) * 128;
        int sw = (row & 3) << 3;
#pragma unroll
        for (int j = 0; j < 4; j++) {
            int col = (ch2 * 32 + j * 8 + 2 * tg) ^ sw;
            *(float2*)&g_h1[base + col] = make_float2(tfh(c2[mf][j][0]), tfh(c2[mf][j][1]));
            *(float2*)&g_h1[base + 8 * 128 + col] = make_float2(tfh(c2[mf][j][2]), tfh(c2[mf][j][3]));
        }
    }

    // s1/d1 epilogue
    float sv[2][2], dv[2][2];
#pragma unroll
    for (int mf = 0; mf < 2; mf++)
#pragma unroll
        for (int rr = 0; rr < 2; rr++) { sv[mf][rr] = 0.0f; dv[mf][rr] = 0.0f; }
#pragma unroll
    for (int mf = 0; mf < 2; mf++)
#pragma unroll
        for (int j = 0; j < 4; j++)
#pragma unroll
            for (int e = 0; e < 4; e++) {
                int col = ch2 * 32 + j * 8 + 2 * tg + (e & 1);
                sv[mf][e >> 1] += c2[mf][j][e] * av[col];
                dv[mf][e >> 1] += c2[mf][j][e] * bv[col];
            }
#pragma unroll
    for (int mf = 0; mf < 2; mf++)
#pragma unroll
        for (int rr = 0; rr < 2; rr++) {
            sv[mf][rr] = qsum(sv[mf][rr]);
            dv[mf][rr] = qsum(dv[mf][rr]);
        }
    if (tg == 0) {
#pragma unroll
        for (int mf = 0; mf < 2; mf++)
#pragma unroll
            for (int rr = 0; rr < 2; rr++) {
                int r = st2 * 32 + mf * 16 + g + rr * 8;
                atomicAdd(&sdb[2 * r], sv[mf][rr]);
                atomicAdd(&sdb[2 * r + 1], dv[mf][rr]);
            }
    }
    __syncthreads();
    if (t < 64) {
        g_s1[b * NN + nb + t] = sdb[2 * t] * LOG2E;
        g_d1[b * NN + nb + t] = sdb[2 * t + 1] * LOG2E;
    }
}

// ------------------------- fused attn1 + tail -------------------------
#define A1T_SMEM ((17920 + 8192) * 4)

// A buffers hold tf32 BITS. Chunk 0 of Wt must already be issued+committed by the
// caller (or by the previous stage's prefetch). Issues Wnext's chunk 0 (into buf 0)
// during the final chunk. ONE sync per chunk; caller must sync after return before
// touching the A region.
__device__ __forceinline__ void tail_mm(const float* __restrict__ Wt,
                                        const float* __restrict__ Wnext,
                                        const float* A, int astride, int K,
                                        float* ws, float c[2][4][4],
                                        int st, int ch, int g, int tg, int lane, int t) {
    int q = lane >> 3, lr = lane & 7;
    int rowoff = (q & 1) * 8 + lr, colblk = (q >> 1) * 4;
    unsigned abase[2];
#pragma unroll
    for (int mf = 0; mf < 2; mf++)
        abase[mf] = sptr(A + (st * 32 + mf * 16 + rowoff) * astride + colblk);

    int NC = K >> 5;
    for (int kt = 0; kt < NC; kt++) {
        CP_WAIT(0);
        __syncthreads();
        if (kt + 1 < NC) {
            issue_half(ws + ((kt + 1) & 1) * 4096, Wt + (size_t)(kt + 1) * 4096, t);
            CP_COMMIT;
        } else if (Wnext) {
            issue_half(ws, Wnext, t);   // buf0: next stage chunk0 (buf0 reads done pre-sync)
            CP_COMMIT;
        }
        const float* wsb = ws + (kt & 1) * 4096;
        for (int kc = 0; kc < 4; kc++) {
            unsigned a[2][4];
#pragma unroll
            for (int mf = 0; mf < 2; mf++)
                ldsm4(a[mf], abase[mf] + ((kt * 32 + kc * 8) << 2));
            int k0 = kc * 8 + tg, k1 = k0 + 4;
            int sw0 = tg << 3;
#pragma unroll
            for (int j = 0; j < 4; j++) {
                int f = ch * 32 + j * 8 + g;
                unsigned bfr[2];
                bfr[0] = __float_as_uint(wsb[k0 * 128 + (f ^ sw0)]);
                bfr[1] = __float_as_uint(wsb[k1 * 128 + (f ^ sw0)]);
                mma_tf32(c[0][j], a[0], bfr);
                mma_tf32(c[1][j], a[1], bfr);
            }
        }
    }
}

__device__ __forceinline__ void frag_store(float* D, int dstride, float c[2][4][4],
                                           int st, int ch, int g, int tg) {
#pragma unroll
    for (int mf = 0; mf < 2; mf++) {
        int row = st * 32 + mf * 16 + g;
#pragma unroll
        for (int j = 0; j < 4; j++) {
            int col = ch * 32 + j * 8 + 2 * tg;
            *(float2*)&D[row * dstride + col] = make_float2(c[mf][j][0], c[mf][j][1]);
            *(float2*)&D[(row + 8) * dstride + col] = make_float2(c[mf][j][2], c[mf][j][3]);
        }
    }
}

__device__ __forceinline__ void frag_zero(float c[2][4][4]) {
#pragma unroll
    for (int mf = 0; mf < 2; mf++)
#pragma unroll
        for (int j = 0; j < 4; j++)
#pragma unroll
            for (int e = 0; e < 4; e++) c[mf][j][e] = 0.0f;
}

__global__ __launch_bounds__(256, 2) void k_a1tail(const float* __restrict__ x,
                       const float* __restrict__ ln1g, const float* __restrict__ ln1b,
                       const float* __restrict__ linb,
                       const float* __restrict__ meb0, const float* __restrict__ meb1,
                       const float* __restrict__ ln2g, const float* __restrict__ ln2b,
                       const float* __restrict__ ohb,
                       const float* __restrict__ ln3g, const float* __restrict__ ln3b,
                       float* __restrict__ out) {
    extern __shared__ float sm[];
    float* sH = sm;                      // 2 x 64x128
    float* sd = sH + 16384;              // 512
    unsigned long long* mkq = (unsigned long long*)(sd + 512);  // 64 x 8
    float* ts = sm;                      // stride 260 (aliases sH/sd after attn)
    float* ms = sm;                      // stride 132
    float* us = sm + 8448;               // stride 132
    float* ws = sm + 17920;              // 2 x 32x128 weight chunks

    int b = blockIdx.y, nb = blockIdx.x * 64;
    int t = threadIdx.x, cq = t & 3, nl = t >> 2;
    int w = t >> 5, lane = t & 31, g = lane >> 2, tg = lane & 3;

    // ======== attn1 phase ========
    {
        int st = w & 3, ch = w >> 2;
        const float* Hsrc = g_h1 + (size_t)b * NN * 128;
        issue_tile(sH, Hsrc, t);
        CP_COMMIT;

        for (int i = t; i < 512; i += 256) sd[i] = g_d1[b * NN + i];
        {
            const unsigned long long* gq =
                (const unsigned long long*)(g_mask + (size_t)(b * NN + nb) * NW);
            for (int i = t; i < 512; i += 256) mkq[i] = gq[i];
        }

        int r0 = st * 16 + g, r1 = r0 + 8;
        float s0v = g_s1[b * NN + nb + r0];
        float s1v = g_s1[b * NN + nb + r1];
        float S0 = 0.0f, S1 = 0.0f;
        float c[8][4];
#pragma unroll
        for (int j = 0; j < 8; j++)
#pragma unroll
            for (int e = 0; e < 4; e++) c[j][e] = 0.0f;

        for (int mt = 0; mt < 8; mt++) {
            CP_WAIT(0);
            __syncthreads();
            if (mt + 1 < 8) {
                issue_tile(sH + ((mt + 1) & 1) * 8192, Hsrc + (size_t)(mt + 1) * 8192, t);
                CP_COMMIT;
            }
            const float* Hb = sH + (mt & 1) * 8192;
            unsigned long long mw0 = mkq[r0 * 8 + mt];
            unsigned long long mw1 = mkq[r1 * 8 + mt];
            const float* dmt = sd + mt * 64;

#pragma unroll
            for (int kc = 0; kc < 8; kc++) {
                int c0 = kc * 8 + tg, c1 = c0 + 4;
                float d0 = dmt[c0], d1 = dmt[c1];
                float z0 = s0v + d0, z1 = s1v + d0;
                float z2 = s0v + d1, z3 = s1v + d1;
                float p0 = ((mw0 >> c0) & 1ull) ? ex2f(fmaxf(z0, 0.2f * z0)) : 0.0f;
                float p1 = ((mw1 >> c0) & 1ull) ? ex2f(fmaxf(z1, 0.2f * z1)) : 0.0f;
                float p2 = ((mw0 >> c1) & 1ull) ? ex2f(fmaxf(z2, 0.2f * z2)) : 0.0f;
                float p3 = ((mw1 >> c1) & 1ull) ? ex2f(fmaxf(z3, 0.2f * z3)) : 0.0f;
                S0 += p0 + p2;
                S1 += p1 + p3;
                unsigned a[4] = { f2tf(p0), f2tf(p1), f2tf(p2), f2tf(p3) };
                int sw0 = tg << 3;
#pragma unroll
                for (int j = 0; j < 8; j++) {
                    int f = ch * 64 + j * 8 + g;
                    unsigned bfr[2];
                    bfr[0] = __float_as_uint(Hb[c0 * 128 + (f ^ sw0)]);
                    bfr[1] = __float_as_uint(Hb[c1 * 128 + (f ^ sw0)]);
                    mma_tf32(c[j], a, bfr);
                }
            }
        }
        S0 = qsum(S0); S1 = qsum(S1);
        float inv0 = 1.0f / S0, inv1 = 1.0f / S1;

        __syncthreads();   // everyone done reading sH/sd; ts overwrite is safe

        // x -> ts cols 0..127 (async); mm1 weight chunk0 prefetch; m1 from registers
        for (int i = t; i < 2048; i += 256) {
            int r = i >> 5, c4 = (i & 31) * 4;
            cpa16(sptr(ts + r * 260 + c4), x + ((size_t)(b * NN + nb) + r) * 128 + c4);
        }
        CP_COMMIT;
        issue_half(ws, g_wtf + 4 * 8192, t);   // mm1 chunk0 (linW rows 0..31)
        CP_COMMIT;
#pragma unroll
        for (int j = 0; j < 8; j++) {
            int col = 128 + ch * 64 + j * 8 + 2 * tg;
            *(float2*)&ts[r0 * 260 + col] = make_float2(c[j][0] * inv0, c[j][1] * inv0);
            *(float2*)&ts[(r0 + 8) * 260 + col] = make_float2(c[j][2] * inv1, c[j][3] * inv1);
        }
        CP_WAIT(1);        // x arrived; mm1 chunk0 may still be in flight
        __syncthreads();
    }

    // ======== tail phase ========
    int st = w & 1, ch = w >> 1;

    // LN1 over 256 (stats on raw fp32; output stored as tf32 bits for mm1)
    float sum = 0, sq = 0;
#pragma unroll 8
    for (int i = 0; i < 64; i++) {
        float v = ts[nl * 260 + cq * 64 + i];
        sum += v; sq += v * v;
    }
    sum = qsum(sum); sq = qsum(sq);
    float mu = sum * (1.0f / 256.0f);
    float rstd = rsqrtf(sq * (1.0f / 256.0f) - mu * mu + 1e-5f);
#pragma unroll 8
    for (int i = 0; i < 64; i++) {
        int j = cq * 64 + i;
        float v = ts[nl * 260 + j];
        ts[nl * 260 + j] = tfh((v - mu) * rstd * ln1g[j] + ln1b[j]);
    }

    float c[2][4][4];
    // mm1: m = LN1 @ linW  (prefetches meW0 chunk0 during its last chunk)
    frag_zero(c);
    tail_mm(g_wtf + 4 * 8192, g_wtf + 8 * 8192, ts, 260, 256,
            ws, c, st, ch, g, tg, lane, t);
    __syncthreads();                   // all warps done reading ts (aliases ms)
    frag_store(ms, 132, c, st, ch, g, tg);
    __syncthreads();
    float mreg[32];
#pragma unroll
    for (int d = 0; d < 32; d++) {
        int o = cq * 32 + d;
        mreg[d] = ms[nl * 132 + o] + linb[o];
        ms[nl * 132 + o] = tfh(mreg[d]);
    }

    // mm2: u = gelu(m @ meW0 + meb0)  (prefetches meW1 chunk0)
    frag_zero(c);
    tail_mm(g_wtf + 8 * 8192, g_wtf + 10 * 8192, ms, 132, 128,
            ws, c, st, ch, g, tg, lane, t);
    __syncthreads();
    frag_store(us, 132, c, st, ch, g, tg);
    __syncthreads();
#pragma unroll
    for (int d = 0; d < 32; d++) {
        int o = cq * 32 + d;
        us[nl * 132 + o] = tfh(gelu_exact(us[nl * 132 + o] + meb0[o]));
    }

    // mm3: enc = u @ meW1; r = m + enc + meb1; LN2 -> us (tf32)  (prefetches ohW chunk0)
    frag_zero(c);
    tail_mm(g_wtf + 10 * 8192, g_wtf + 12 * 8192, us, 132, 128,
            ws, c, st, ch, g, tg, lane, t);
    __syncthreads();
    frag_store(ms, 132, c, st, ch, g, tg);
    __syncthreads();
    float a3[32];
    sum = 0; sq = 0;
#pragma unroll
    for (int d = 0; d < 32; d++) {
        int o = cq * 32 + d;
        a3[d] = ms[nl * 132 + o] + meb1[o] + mreg[d];
        sum += a3[d]; sq += a3[d] * a3[d];
    }
    sum = qsum(sum); sq = qsum(sq);
    mu = sum * (1.0f / 128.0f);
    rstd = rsqrtf(sq * (1.0f / 128.0f) - mu * mu + 1e-5f);
#pragma unroll
    for (int d = 0; d < 32; d++) {
        int o = cq * 32 + d;
        us[nl * 132 + o] = tfh((a3[d] - mu) * rstd * ln2g[o] + ln2b[o]);
    }

    // mm4: v = gelu(us @ ohW + ohb); LN3; out
    frag_zero(c);
    tail_mm(g_wtf + 12 * 8192, nullptr, us, 132, 128,
            ws, c, st, ch, g, tg, lane, t);
    __syncthreads();
    frag_store(ms, 132, c, st, ch, g, tg);
    __syncthreads();
    float a4[32];
    sum = 0; sq = 0;
#pragma unroll
    for (int d = 0; d < 32; d++) {
        int o = cq * 32 + d;
        float v = gelu_exact(ms[nl * 132 + o] + ohb[o]);
        a4[d] = v;
        sum += v; sq += v * v;
    }
    sum = qsum(sum); sq = qsum(sq);
    mu = sum * (1.0f / 128.0f);
    rstd = rsqrtf(sq * (1.0f / 128.0f) - mu * mu + 1e-5f);

    float* op = out + ((size_t)b * NN + nb + nl) * 128 + cq * 32;
#pragma unroll
    for (int d4 = 0; d4 < 8; d4++) {
        float r0 = (a4[4 * d4 + 0] - mu) * rstd * ln3g[cq * 32 + 4 * d4 + 0] + ln3b[cq * 32 + 4 * d4 + 0];
        float r1 = (a4[4 * d4 + 1] - mu) * rstd * ln3g[cq * 32 + 4 * d4 + 1] + ln3b[cq * 32 + 4 * d4 + 1];
        float r2 = (a4[4 * d4 + 2] - mu) * rstd * ln3g[cq * 32 + 4 * d4 + 2] + ln3b[cq * 32 + 4 * d4 + 2];
        float r3 = (a4[4 * d4 + 3] - mu) * rstd * ln3g[cq * 32 + 4 * d4 + 3] + ln3b[cq * 32 + 4 * d4 + 3];
        ((float4*)op)[d4] = make_float4(r0, r1, r2, r3);
    }
}

// ------------------------- launch -------------------------
extern "C" void kernel_launch(void* const* d_in, const int* in_sizes, int n_in,
                              void* d_out, int out_size) {
    const float* x    = (const float*)d_in[0];
    const int*   grp  = (const int*)  d_in[1];
    const float* W0   = (const float*)d_in[2];
    const float* as0  = (const float*)d_in[3];
    const float* ad0  = (const float*)d_in[4];
    const float* W1   = (const float*)d_in[5];
    const float* as1  = (const float*)d_in[6];
    const float* ad1  = (const float*)d_in[7];
    const float* ln1g = (const float*)d_in[8];
    const float* ln1b = (const float*)d_in[9];
    const float* linW = (const float*)d_in[10];
    const float* linb = (const float*)d_in[11];
    const float* meW0 = (const float*)d_in[12];
    const float* meb0 = (const float*)d_in[13];
    const float* meW1 = (const float*)d_in[14];
    const float* meb1 = (const float*)d_in[15];
    const float* ln2g = (const float*)d_in[16];
    const float* ln2b = (const float*)d_in[17];
    const float* ohW  = (const float*)d_in[18];
    const float* ohb  = (const float*)d_in[19];
    const float* ln3g = (const float*)d_in[20];
    const float* ln3b = (const float*)d_in[21];
    float* out = (float*)d_out;

    cudaFuncSetAttribute(k_proj0, cudaFuncAttributeMaxDynamicSharedMemorySize, P0_SMEM);
    cudaFuncSetAttribute(k_attn0, cudaFuncAttributeMaxDynamicSharedMemorySize, A0_SMEM);
    cudaFuncSetAttribute(k_a1tail, cudaFuncAttributeMaxDynamicSharedMemorySize, A1T_SMEM);

    dim3 grid(NN / 64, BB);
    k_wprep<<<112, 256>>>(W0, W1, linW, meW0, meW1, ohW);
    k_proj0<<<grid, 256, P0_SMEM>>>(x, as0, ad0);
    k_attn0<<<grid, 256, A0_SMEM>>>(grp, as1, ad1);
    k_a1tail<<<grid, 256, A1T_SMEM>>>(x, ln1g, ln1b, linb, meb0, meb1,
                                      ln2g, ln2b, ohb, ln3g, ln3b, out);
}